// round 1
// baseline (speedup 1.0000x reference)
#include <cuda_runtime.h>
#include <math.h>

#define S 4096
#define D 1024
#define H 16
#define DH 64
#define F 4096
#define EPSF 1e-6f

// ---------------- scratch (device globals: alloc-free) ----------------
__device__ float g_xn[S * D];
__device__ float g_h [S * F];
__device__ float g_q [S * D];
__device__ float g_k [S * D];
__device__ float g_v [S * D];
__device__ float g_o [S * D];

// ---------------- LayerNorm over D=1024, block per row ----------------
__global__ void ln_kernel(const float* __restrict__ x,
                          const float* __restrict__ gamma,
                          const float* __restrict__ beta,
                          float* __restrict__ y) {
    __shared__ float sh[8];
    __shared__ float stat;
    int row = blockIdx.x;
    int t = threadIdx.x;
    const float4* xr = (const float4*)(x + (size_t)row * D);
    float4 xv = xr[t];

    float s = xv.x + xv.y + xv.z + xv.w;
#pragma unroll
    for (int o = 16; o > 0; o >>= 1) s += __shfl_xor_sync(0xffffffffu, s, o);
    if ((t & 31) == 0) sh[t >> 5] = s;
    __syncthreads();
    if (t == 0) {
        float tot = 0.f;
#pragma unroll
        for (int i = 0; i < 8; i++) tot += sh[i];
        stat = tot * (1.f / (float)D);
    }
    __syncthreads();
    float mean = stat;

    float d0 = xv.x - mean, d1 = xv.y - mean, d2 = xv.z - mean, d3 = xv.w - mean;
    float sq = d0 * d0 + d1 * d1 + d2 * d2 + d3 * d3;
#pragma unroll
    for (int o = 16; o > 0; o >>= 1) sq += __shfl_xor_sync(0xffffffffu, sq, o);
    __syncthreads();           // protect sh reuse
    if ((t & 31) == 0) sh[t >> 5] = sq;
    __syncthreads();
    if (t == 0) {
        float tot = 0.f;
#pragma unroll
        for (int i = 0; i < 8; i++) tot += sh[i];
        stat = rsqrtf(tot * (1.f / (float)D) + EPSF);
    }
    __syncthreads();
    float rinv = stat;

    float4 gv = ((const float4*)gamma)[t];
    float4 bv = ((const float4*)beta)[t];
    float4 o4;
    o4.x = d0 * rinv * gv.x + bv.x;
    o4.y = d1 * rinv * gv.y + bv.y;
    o4.z = d2 * rinv * gv.z + bv.z;
    o4.w = d3 * rinv * gv.w + bv.w;
    ((float4*)(y + (size_t)row * D))[t] = o4;
}

// ---------------- per-head LN (Dh=64, no bias), thread per row ----------------
__global__ void qknorm_kernel(float* __restrict__ tq, const float* __restrict__ scale) {
    int row = blockIdx.x * blockDim.x + threadIdx.x;   // S*H rows exactly
    float* p = tq + (size_t)row * DH;
    float4 v[16];
    float s = 0.f;
#pragma unroll
    for (int i = 0; i < 16; i++) {
        v[i] = ((const float4*)p)[i];
        s += v[i].x + v[i].y + v[i].z + v[i].w;
    }
    float mean = s * (1.f / (float)DH);
    float sq = 0.f;
#pragma unroll
    for (int i = 0; i < 16; i++) {
        v[i].x -= mean; v[i].y -= mean; v[i].z -= mean; v[i].w -= mean;
        sq += v[i].x * v[i].x + v[i].y * v[i].y + v[i].z * v[i].z + v[i].w * v[i].w;
    }
    float r = rsqrtf(sq * (1.f / (float)DH) + EPSF);
#pragma unroll
    for (int i = 0; i < 16; i++) {
        float4 sc = ((const float4*)scale)[i];
        float4 o4;
        o4.x = v[i].x * r * sc.x;
        o4.y = v[i].y * r * sc.y;
        o4.z = v[i].z * r * sc.z;
        o4.w = v[i].w * r * sc.w;
        ((float4*)p)[i] = o4;
    }
}

// ---------------- GELU (tanh approx, matches jax.nn.gelu default) ----------------
__device__ __forceinline__ float gelu_f(float x) {
    float x3 = x * x * x;
    return 0.5f * x * (1.f + tanhf(0.7978845608028654f * (x + 0.044715f * x3)));
}

// ---------------- SGEMM: C = epilogue(A[M,K] @ B[K,N]) ----------------
// MODE 0: C = acc + bias    MODE 1: C = gelu(acc + bias)    MODE 2: C += acc
template <int MODE>
__global__ void __launch_bounds__(256) sgemm_kernel(
    const float* __restrict__ A, const float* __restrict__ B,
    const float* __restrict__ bias, float* __restrict__ C,
    int M, int N, int K)
{
    __shared__ float As[8][128];
    __shared__ float Bs[8][128];
    int tid = threadIdx.x;
    int bm = blockIdx.y << 7, bn = blockIdx.x << 7;

    int arow = tid >> 1,  acol = (tid & 1) << 2;   // 128 x 8 A tile
    int brow = tid >> 5,  bcol = (tid & 31) << 2;  // 8 x 128 B tile
    int tm = (tid >> 4) << 3, tn = (tid & 15) << 3;

    const float* Ap = A + (size_t)(bm + arow) * K + acol;
    const float* Bp = B + (size_t)brow * N + bn + bcol;

    float acc[8][8];
#pragma unroll
    for (int i = 0; i < 8; i++)
#pragma unroll
        for (int j = 0; j < 8; j++) acc[i][j] = 0.f;

    int nk = K >> 3;
    for (int kb = 0; kb < nk; kb++) {
        float4 a4 = *(const float4*)Ap;
        float4 b4 = *(const float4*)Bp;
        As[acol + 0][arow] = a4.x;
        As[acol + 1][arow] = a4.y;
        As[acol + 2][arow] = a4.z;
        As[acol + 3][arow] = a4.w;
        *(float4*)&Bs[brow][bcol] = b4;
        __syncthreads();
#pragma unroll
        for (int kk = 0; kk < 8; kk++) {
            float ra[8], rb[8];
            *(float4*)&ra[0] = *(float4*)&As[kk][tm];
            *(float4*)&ra[4] = *(float4*)&As[kk][tm + 4];
            *(float4*)&rb[0] = *(float4*)&Bs[kk][tn];
            *(float4*)&rb[4] = *(float4*)&Bs[kk][tn + 4];
#pragma unroll
            for (int i = 0; i < 8; i++)
#pragma unroll
                for (int j = 0; j < 8; j++) acc[i][j] += ra[i] * rb[j];
        }
        __syncthreads();
        Ap += 8;
        Bp += (size_t)8 * N;
    }

#pragma unroll
    for (int i = 0; i < 8; i++) {
        float* cp = C + (size_t)(bm + tm + i) * N + bn + tn;
        if (MODE == 2) {
            float4 c0 = *(float4*)cp;
            float4 c1 = *(float4*)(cp + 4);
            c0.x += acc[i][0]; c0.y += acc[i][1]; c0.z += acc[i][2]; c0.w += acc[i][3];
            c1.x += acc[i][4]; c1.y += acc[i][5]; c1.z += acc[i][6]; c1.w += acc[i][7];
            *(float4*)cp = c0;
            *(float4*)(cp + 4) = c1;
        } else {
            const float* bp = bias + bn + tn;
            float4 bb0 = *(const float4*)bp;
            float4 bb1 = *(const float4*)(bp + 4);
            float v0 = acc[i][0] + bb0.x, v1 = acc[i][1] + bb0.y;
            float v2 = acc[i][2] + bb0.z, v3 = acc[i][3] + bb0.w;
            float v4 = acc[i][4] + bb1.x, v5 = acc[i][5] + bb1.y;
            float v6 = acc[i][6] + bb1.z, v7 = acc[i][7] + bb1.w;
            if (MODE == 1) {
                v0 = gelu_f(v0); v1 = gelu_f(v1); v2 = gelu_f(v2); v3 = gelu_f(v3);
                v4 = gelu_f(v4); v5 = gelu_f(v5); v6 = gelu_f(v6); v7 = gelu_f(v7);
            }
            float4 c0 = {v0, v1, v2, v3};
            float4 c1 = {v4, v5, v6, v7};
            *(float4*)cp = c0;
            *(float4*)(cp + 4) = c1;
        }
    }
}

// ---------------- causal flash attention, thread per (head, query) ----------------
__global__ void __launch_bounds__(128) attn_kernel(
    const float* __restrict__ q, const float* __restrict__ k,
    const float* __restrict__ v, float* __restrict__ o)
{
    __shared__ float Ks[64][64];
    __shared__ float Vs[64][64];
    int head = blockIdx.y;
    int qi = blockIdx.x * 128 + threadIdx.x;

    float qr[64];
    const float* qp = q + (size_t)qi * D + head * DH;
#pragma unroll
    for (int j = 0; j < 16; j++) {
        float4 t4 = ((const float4*)qp)[j];
        qr[4 * j + 0] = t4.x * 0.125f;   // 1/sqrt(Dh) folded into q
        qr[4 * j + 1] = t4.y * 0.125f;
        qr[4 * j + 2] = t4.z * 0.125f;
        qr[4 * j + 3] = t4.w * 0.125f;
    }

    float oa[64];
#pragma unroll
    for (int d = 0; d < 64; d++) oa[d] = 0.f;
    float m = -INFINITY, l = 0.f;

    int ntiles = blockIdx.x * 2 + 2;   // key tiles 0 .. 2*bx+1 (causal)
    int r = threadIdx.x >> 1;
    int c0 = (threadIdx.x & 1) * 32;

    for (int kt = 0; kt < ntiles; kt++) {
        const float* kp = k + (size_t)(kt * 64 + r) * D + head * DH + c0;
        const float* vp = v + (size_t)(kt * 64 + r) * D + head * DH + c0;
#pragma unroll
        for (int j = 0; j < 8; j++) {
            ((float4*)&Ks[r][c0])[j] = ((const float4*)kp)[j];
            ((float4*)&Vs[r][c0])[j] = ((const float4*)vp)[j];
        }
        __syncthreads();

        int jmax = qi - kt * 64 + 1;
        if (jmax > 64) jmax = 64;
        for (int j = 0; j < jmax; j++) {
            float s0 = 0.f, s1 = 0.f, s2 = 0.f, s3 = 0.f;
#pragma unroll
            for (int d = 0; d < 64; d += 4) {
                s0 += qr[d + 0] * Ks[j][d + 0];
                s1 += qr[d + 1] * Ks[j][d + 1];
                s2 += qr[d + 2] * Ks[j][d + 2];
                s3 += qr[d + 3] * Ks[j][d + 3];
            }
            float s = (s0 + s1) + (s2 + s3);
            float p;
            if (s > m) {
                float alpha = __expf(m - s);   // exp(-inf)=0 handles first key
#pragma unroll
                for (int d = 0; d < 64; d++) oa[d] *= alpha;
                l *= alpha;
                m = s;
                p = 1.f;
            } else {
                p = __expf(s - m);
            }
            l += p;
#pragma unroll
            for (int d = 0; d < 64; d++) oa[d] += p * Vs[j][d];
        }
        __syncthreads();
    }

    float inv = 1.f / l;
    float* op = o + (size_t)qi * D + head * DH;
#pragma unroll
    for (int j = 0; j < 16; j++) {
        float4 t4;
        t4.x = oa[4 * j + 0] * inv;
        t4.y = oa[4 * j + 1] * inv;
        t4.z = oa[4 * j + 2] * inv;
        t4.w = oa[4 * j + 3] * inv;
        ((float4*)op)[j] = t4;
    }
}

// ---------------- out = x + b_mo + b_ao (GEMMs then accumulate on top) ----------------
__global__ void init_out_kernel(const float* __restrict__ x,
                                const float* __restrict__ bmo,
                                const float* __restrict__ bao,
                                float* __restrict__ out) {
    int i = blockIdx.x * blockDim.x + threadIdx.x;
    int col = i & (D - 1);
    out[i] = x[i] + bmo[col] + bao[col];
}

// ---------------- launch ----------------
extern "C" void kernel_launch(void* const* d_in, const int* in_sizes, int n_in,
                              void* d_out, int out_size) {
    const float* x        = (const float*)d_in[0];
    // d_in[1] = mask: causal tril, implemented analytically -> ignored
    const float* ln_scale = (const float*)d_in[2];
    const float* ln_bias  = (const float*)d_in[3];
    const float* w_in     = (const float*)d_in[4];
    const float* b_in     = (const float*)d_in[5];
    const float* wq       = (const float*)d_in[6];
    const float* bq       = (const float*)d_in[7];
    const float* wk       = (const float*)d_in[8];
    const float* bk       = (const float*)d_in[9];
    const float* wv       = (const float*)d_in[10];
    const float* bv       = (const float*)d_in[11];
    const float* qn       = (const float*)d_in[12];
    const float* kn       = (const float*)d_in[13];
    const float* w_mo     = (const float*)d_in[14];
    const float* b_mo     = (const float*)d_in[15];
    const float* w_ao     = (const float*)d_in[16];
    const float* b_ao     = (const float*)d_in[17];
    float* out = (float*)d_out;

    float *xn, *h, *q, *k, *v, *o;
    cudaGetSymbolAddress((void**)&xn, g_xn);
    cudaGetSymbolAddress((void**)&h,  g_h);
    cudaGetSymbolAddress((void**)&q,  g_q);
    cudaGetSymbolAddress((void**)&k,  g_k);
    cudaGetSymbolAddress((void**)&v,  g_v);
    cudaGetSymbolAddress((void**)&o,  g_o);

    // 1. PreNorm
    ln_kernel<<<S, 256>>>(x, ln_scale, ln_bias, xn);

    // 2. MLP input + GELU: h = gelu(xn @ w_in + b_in)
    sgemm_kernel<1><<<dim3(F / 128, S / 128), 256>>>(xn, w_in, b_in, h, S, F, D);

    // 3. QKV projections
    sgemm_kernel<0><<<dim3(D / 128, S / 128), 256>>>(xn, wq, bq, q, S, D, D);
    sgemm_kernel<0><<<dim3(D / 128, S / 128), 256>>>(xn, wk, bk, k, S, D, D);
    sgemm_kernel<0><<<dim3(D / 128, S / 128), 256>>>(xn, wv, bv, v, S, D, D);

    // 4. qk-norm (per-head LN, no bias)
    qknorm_kernel<<<(S * H) / 256, 256>>>(q, qn);
    qknorm_kernel<<<(S * H) / 256, 256>>>(k, kn);

    // 5. causal attention
    attn_kernel<<<dim3(S / 128, H), 128>>>(q, k, v, o);

    // 6. out = x + b_mo + b_ao, then += h@w_mo, += o@w_ao
    init_out_kernel<<<(S * D) / 256, 256>>>(x, b_mo, b_ao, out);
    sgemm_kernel<2><<<dim3(D / 128, S / 128), 256>>>(h, w_mo, nullptr, out, S, D, F);
    sgemm_kernel<2><<<dim3(D / 128, S / 128), 256>>>(o, w_ao, nullptr, out, S, D, D);
}